// round 12
// baseline (speedup 1.0000x reference)
#include <cuda_runtime.h>
#include <cuda_bf16.h>
#include <cstdint>

#define BQ 16
#define CC 512
#define NN 1024
#define NH 8
#define HD 64
#define NG 32
#define CPG 16
#define EPSV 1e-5f
#define CCW 256   // words (bf16x2) per 512-channel row

// ---------------------------------------------------------------------------
// helpers
// ---------------------------------------------------------------------------
__device__ __forceinline__ uint32_t packbf(float lo, float hi) {
    __nv_bfloat162 h = __floats2bfloat162_rn(lo, hi);
    return *reinterpret_cast<uint32_t*>(&h);
}
__device__ __forceinline__ float ex2f(float x) {
    float r;
    asm("ex2.approx.ftz.f32 %0, %1;" : "=f"(r) : "f"(x));
    return r;
}
__device__ __forceinline__ void mma_bf16(float* c, const uint32_t* a,
                                         const uint32_t* b) {
    asm volatile(
        "mma.sync.aligned.m16n8k16.row.col.f32.bf16.bf16.f32 "
        "{%0,%1,%2,%3}, {%4,%5,%6,%7}, {%8,%9}, {%0,%1,%2,%3};"
        : "+f"(c[0]), "+f"(c[1]), "+f"(c[2]), "+f"(c[3])
        : "r"(a[0]), "r"(a[1]), "r"(a[2]), "r"(a[3]), "r"(b[0]), "r"(b[1]));
}
__device__ __forceinline__ void ldm_x4(uint32_t* r, const uint32_t* p) {
    uint32_t a = (uint32_t)__cvta_generic_to_shared(p);
    asm volatile(
        "ldmatrix.sync.aligned.m8n8.x4.shared.b16 {%0,%1,%2,%3}, [%4];"
        : "=r"(r[0]), "=r"(r[1]), "=r"(r[2]), "=r"(r[3]) : "r"(a));
}
__device__ __forceinline__ void cp16(void* sdst, const void* gsrc) {
    uint32_t s = (uint32_t)__cvta_generic_to_shared(sdst);
    asm volatile("cp.async.cg.shared.global [%0], [%1], 16;" :: "r"(s), "l"(gsrc));
}
#define CP_COMMIT() asm volatile("cp.async.commit_group;")
#define CP_WAIT(n) asm volatile("cp.async.wait_group %0;" :: "n"(n))

#define LOG2E 1.44269504f

// ---------------------------------------------------------------------------
// Scratch (bf16x2 words)
// ---------------------------------------------------------------------------
__device__ uint32_t g_xnT[(size_t)BQ * NN * CCW];    // [B,N,C/2]
__device__ uint32_t g_qkT[(size_t)BQ * NN * 2 * CCW];// [B,N, q | k]
__device__ uint32_t g_vN[(size_t)BQ * CC * (NN / 2)];// [B, vch, N/2]
__device__ uint32_t g_attT[(size_t)BQ * NN * CCW];   // [B,N,C/2]
__device__ uint32_t g_wq[(size_t)3 * CC * CCW];      // qkv_w bf16
__device__ uint32_t g_wp[(size_t)CC * CCW];          // proj_w bf16

// ---------------------------------------------------------------------------
// both weights -> bf16 in one launch
// ---------------------------------------------------------------------------
__global__ void w2bf16_all(const float4* __restrict__ qw,
                           const float4* __restrict__ pw,
                           uint2* __restrict__ oq, uint2* __restrict__ op) {
    const int nq = 3 * CC * CC / 4;
    const int np = CC * CC / 4;
    int i = blockIdx.x * 256 + threadIdx.x;
    if (i < nq) {
        float4 v = qw[i];
        oq[i] = make_uint2(packbf(v.x, v.y), packbf(v.z, v.w));
    } else if (i - nq < np) {
        float4 v = pw[i - nq];
        op[i - nq] = make_uint2(packbf(v.x, v.y), packbf(v.z, v.w));
    }
}

// ---------------------------------------------------------------------------
// GroupNorm, single global pass (SMEM-cached group). xnT[b][n][cword].
// ---------------------------------------------------------------------------
#define GN_STRIDE 1028
#define GN_SMEM (16 * GN_STRIDE * 4)

__global__ __launch_bounds__(256) void groupnorm_kernel(
    const float* __restrict__ x, const float* __restrict__ gamma,
    const float* __restrict__ beta, uint32_t* __restrict__ xnT) {
    extern __shared__ float tile[];
    __shared__ float rs[8], rss[8];

    const int b = blockIdx.x / NG;
    const int g = blockIdx.x % NG;
    const float* px = x + ((size_t)b * CC + g * CPG) * NN;
    const int tid = threadIdx.x;
    const int M = CPG * NN;  // 16384

    float s = 0.f, ss = 0.f;
    for (int i = tid; i < M / 4; i += 256) {
        float4 v = ((const float4*)px)[i];
        int c = i >> 8;
        int n4 = (i & 255) * 4;
        *(float4*)&tile[c * GN_STRIDE + n4] = v;
        s += v.x + v.y + v.z + v.w;
        ss += v.x * v.x + v.y * v.y + v.z * v.z + v.w * v.w;
    }
#pragma unroll
    for (int o = 16; o; o >>= 1) {
        s += __shfl_xor_sync(0xffffffffu, s, o);
        ss += __shfl_xor_sync(0xffffffffu, ss, o);
    }
    int wid = tid / 32, lid = tid % 32;
    if (lid == 0) { rs[wid] = s; rss[wid] = ss; }
    __syncthreads();
    if (wid == 0) {
        s = (lid < 8) ? rs[lid] : 0.f;
        ss = (lid < 8) ? rss[lid] : 0.f;
#pragma unroll
        for (int o = 4; o; o >>= 1) {
            s += __shfl_xor_sync(0xffffffffu, s, o);
            ss += __shfl_xor_sync(0xffffffffu, ss, o);
        }
        if (lid == 0) { rs[0] = s; rss[0] = ss; }
    }
    __syncthreads();
    const float mean = rs[0] / (float)M;
    const float var = rss[0] / (float)M - mean * mean;
    const float rstd = rsqrtf(var + EPSV);

    const int cw = tid & 7;
    const float ga0 = gamma[g * CPG + 2 * cw] * rstd;
    const float be0 = beta[g * CPG + 2 * cw];
    const float ga1 = gamma[g * CPG + 2 * cw + 1] * rstd;
    const float be1 = beta[g * CPG + 2 * cw + 1];
    const float* r0 = &tile[(2 * cw) * GN_STRIDE];
    const float* r1 = r0 + GN_STRIDE;
    uint32_t* og = xnT + (size_t)b * NN * CCW + g * 8 + cw;

#pragma unroll
    for (int rep = 0; rep < 32; rep++) {
        int n = rep * 32 + (tid >> 3);
        float v0 = (r0[n] - mean) * ga0 + be0;
        float v1 = (r1[n] - mean) * ga1 + be1;
        og[(size_t)n * CCW] = packbf(v0, v1);
    }
}

// ---------------------------------------------------------------------------
// bf16 mma GEMM, CTA 128x256, warp tile 64x64, 3-stage cp.async, BK=64.
// MODE 0: fp32 out + bias + residual (proj)
// MODE 1: qkv — q/k transposed+packed to qkT (q scaled by 1/8*log2e), v to vN.
// ---------------------------------------------------------------------------
#define BKW 32
#define PADW 36
#define A_TILE_W (128 * PADW)             // 4608 words
#define B_TILE_W (256 * PADW)             // 9216 words
#define STAGE_W (A_TILE_W + B_TILE_W)     // 13824 words
#define GEMM_SMEM (3 * STAGE_W * 4)       // 165888 B

template <int MODE>
__global__ __launch_bounds__(256, 1) void gemm_mma(
    const uint32_t* __restrict__ W, const float* __restrict__ bias,
    const uint32_t* __restrict__ XT, const float* __restrict__ res,
    float* __restrict__ outf, uint32_t* __restrict__ qkT,
    uint32_t* __restrict__ vN, int O) {
    extern __shared__ uint32_t smg[];

    const int tid = threadIdx.x;
    const int wid = tid >> 5, lane = tid & 31;
    const int g = lane >> 2, tig = lane & 3;
    const int wm = wid >> 2, wn = wid & 3;       // warp grid 2m x 4n
    const int b = blockIdx.z, n0 = blockIdx.x * 256, m0 = blockIdx.y * 128;

    const int ri = lane & 7, mi = lane >> 3;
    const int arow = (mi & 1) * 8 + ri, aword = (mi >> 1) * 4;
    const int brow = (mi >> 1) * 8 + ri, bword = (mi & 1) * 4;

    float acc[4][8][4];
#pragma unroll
    for (int i = 0; i < 4; i++)
#pragma unroll
        for (int j = 0; j < 8; j++)
#pragma unroll
            for (int e = 0; e < 4; e++) acc[i][j][e] = 0.f;

    const uint32_t* Wp = W + (size_t)m0 * CCW;
    const uint32_t* Xp = XT + (size_t)b * NN * CCW + (size_t)n0 * CCW;

    // per-stage cp.async: A 1024 cp16 (4/thr), B 2048 cp16 (8/thr)
    auto issue = [&](int buf, int k0w) {
        uint32_t* As = smg + buf * STAGE_W;
        uint32_t* Bs = As + A_TILE_W;
#pragma unroll
        for (int p = 0; p < 4; p++) {
            int idx = p * 256 + tid;
            int r = idx >> 3, w4 = (idx & 7) * 4;
            cp16(&As[r * PADW + w4], &Wp[(size_t)r * CCW + k0w + w4]);
        }
#pragma unroll
        for (int p = 0; p < 8; p++) {
            int idx = p * 256 + tid;
            int r = idx >> 3, w4 = (idx & 7) * 4;
            cp16(&Bs[r * PADW + w4], &Xp[(size_t)r * CCW + k0w + w4]);
        }
    };

    issue(0, 0); CP_COMMIT();
    issue(1, BKW); CP_COMMIT();

    const int NKT = CCW / BKW;  // 8
    for (int kt = 0; kt < NKT; kt++) {
        CP_WAIT(1);
        __syncthreads();
        if (kt + 2 < NKT) issue((kt + 2) % 3, (kt + 2) * BKW);
        CP_COMMIT();

        const uint32_t* As = smg + (kt % 3) * STAGE_W;
        const uint32_t* Bs = As + A_TILE_W;
#pragma unroll
        for (int s = 0; s < 4; s++) {  // 4 k16-steps
            uint32_t af[4][4], bf[8][2];
#pragma unroll
            for (int mt = 0; mt < 4; mt++)
                ldm_x4(af[mt],
                       &As[(wm * 64 + mt * 16 + arow) * PADW + s * 8 + aword]);
#pragma unroll
            for (int np = 0; np < 4; np++) {
                uint32_t t[4];
                ldm_x4(t, &Bs[(wn * 64 + np * 16 + brow) * PADW + s * 8 + bword]);
                bf[2 * np][0] = t[0]; bf[2 * np][1] = t[1];
                bf[2 * np + 1][0] = t[2]; bf[2 * np + 1][1] = t[3];
            }
#pragma unroll
            for (int mt = 0; mt < 4; mt++)
#pragma unroll
                for (int nt = 0; nt < 8; nt++)
                    mma_bf16(acc[mt][nt], af[mt], bf[nt]);
        }
    }

    // epilogue
    if (MODE == 0) {
#pragma unroll
        for (int mt = 0; mt < 4; mt++) {
            const int mA = m0 + wm * 64 + mt * 16 + g;
            const float bvA = bias[mA], bvB = bias[mA + 8];
            float* oA = outf + ((size_t)b * O + mA) * NN + n0;
            float* oB = oA + (size_t)8 * NN;
            const float* rA = res + ((size_t)b * O + mA) * NN + n0;
            const float* rB = rA + (size_t)8 * NN;
#pragma unroll
            for (int nt = 0; nt < 8; nt++) {
                const int nc = wn * 64 + nt * 8 + tig * 2;
                float2 ra = *(const float2*)&rA[nc];
                float2 rb = *(const float2*)&rB[nc];
                float2 vA = make_float2(acc[mt][nt][0] + bvA + ra.x,
                                        acc[mt][nt][1] + bvA + ra.y);
                float2 vB = make_float2(acc[mt][nt][2] + bvB + rb.x,
                                        acc[mt][nt][3] + bvB + rb.y);
                *(float2*)&oA[nc] = vA;
                *(float2*)&oB[nc] = vB;
            }
        }
    } else {
        const int region = m0 >> 9;  // 0=q, 1=k, 2=v
        const float sc = (region == 0) ? 0.125f * LOG2E : 1.0f;
#pragma unroll
        for (int mt = 0; mt < 4; mt++) {
            const int mA = m0 + wm * 64 + mt * 16 + g;
            const float bvA = bias[mA], bvB = bias[mA + 8];
#pragma unroll
            for (int nt = 0; nt < 8; nt++) {
                const int nc = n0 + wn * 64 + nt * 8 + tig * 2;
                float v0 = (acc[mt][nt][0] + bvA) * sc;
                float v1 = (acc[mt][nt][1] + bvA) * sc;
                float v2 = (acc[mt][nt][2] + bvB) * sc;
                float v3 = (acc[mt][nt][3] + bvB) * sc;
                if (region < 2) {
                    float p0 = __shfl_down_sync(0xffffffffu, v0, 4);
                    float p1 = __shfl_down_sync(0xffffffffu, v1, 4);
                    float p2 = __shfl_down_sync(0xffffffffu, v2, 4);
                    float p3 = __shfl_down_sync(0xffffffffu, v3, 4);
                    if (!(g & 1)) {
                        const int cw = mA >> 1;
                        size_t base0 = ((size_t)b * NN + nc) * (2 * CCW);
                        size_t base1 = base0 + 2 * CCW;
                        qkT[base0 + cw]     = packbf(v0, p0);
                        qkT[base0 + cw + 4] = packbf(v2, p2);
                        qkT[base1 + cw]     = packbf(v1, p1);
                        qkT[base1 + cw + 4] = packbf(v3, p3);
                    }
                } else {
                    const int ch = mA - 2 * CC;
                    vN[((size_t)b * CC + ch) * (NN / 2) + (nc >> 1)] =
                        packbf(v0, v1);
                    vN[((size_t)b * CC + ch + 8) * (NN / 2) + (nc >> 1)] =
                        packbf(v2, v3);
                }
            }
        }
    }
}

// ---------------------------------------------------------------------------
// Flash attention bf16 + ldmatrix + double-buffered cp.async K/V (unchanged).
// ---------------------------------------------------------------------------
#define AQ_OFF 0
#define AK_OFF 4608
#define AV_OFF 13824
#define ATTN_SMEM ((13824 + 2 * 4352) * 4)  // 90112 B

__global__ __launch_bounds__(256, 2) void attn_mma(
    const uint32_t* __restrict__ qkT, const uint32_t* __restrict__ vN,
    uint32_t* __restrict__ attT) {
    extern __shared__ uint32_t smw[];
    uint32_t* Qs = smw + AQ_OFF;

    const int qb = blockIdx.x, h = blockIdx.y, b = blockIdx.z;
    const int tid = threadIdx.x, lane = tid & 31;
    const int g = lane >> 2, tig = lane & 3;
    const int w16 = (tid >> 5) * 16;

    const int ri = lane & 7, mi = lane >> 3;
    const int arow = (mi & 1) * 8 + ri, aword = (mi >> 1) * 4;
    const int brow = (mi >> 1) * 8 + ri, bword = (mi & 1) * 4;

    auto issueKV = [&](int buf, int kb) {
        uint32_t* Ks = smw + AK_OFF + buf * 4608;
        uint32_t* Vs = smw + AV_OFF + buf * 4352;
        const uint32_t* kg = qkT + ((size_t)b * NN + kb * 128) * (2 * CCW) +
                             256 + h * 32;
#pragma unroll
        for (int p = 0; p < 4; p++) {
            int idx = p * 256 + tid;
            int n = idx >> 3, q4 = (idx & 7) * 4;
            cp16(&Ks[n * 36 + q4], &kg[(size_t)n * (2 * CCW) + q4]);
        }
        const uint32_t* vg = vN + ((size_t)b * CC + h * 64) * (NN / 2) + kb * 64;
#pragma unroll
        for (int p = 0; p < 4; p++) {
            int idx = p * 256 + tid;
            int dv = idx >> 4, j4 = (idx & 15) * 4;
            cp16(&Vs[dv * 68 + j4], &vg[(size_t)dv * (NN / 2) + j4]);
        }
    };

    {
        const uint32_t* qg = qkT + ((size_t)b * NN + qb * 128) * (2 * CCW) + h * 32;
#pragma unroll
        for (int p = 0; p < 4; p++) {
            int idx = p * 256 + tid;
            int n = idx >> 3, q4 = (idx & 7) * 4;
            cp16(&Qs[n * 36 + q4], &qg[(size_t)n * (2 * CCW) + q4]);
        }
        issueKV(0, 0);
        CP_COMMIT();
    }

    float m0 = -1e30f, m1 = -1e30f, l0 = 0.f, l1 = 0.f;
    float o[8][4];
#pragma unroll
    for (int nt = 0; nt < 8; nt++)
#pragma unroll
        for (int e = 0; e < 4; e++) o[nt][e] = 0.f;

    for (int kb = 0; kb < 8; kb++) {
        __syncthreads();
        if (kb + 1 < 8) {
            issueKV((kb + 1) & 1, kb + 1);
            CP_COMMIT();
            CP_WAIT(1);
        } else {
            CP_WAIT(0);
        }
        __syncthreads();

        const uint32_t* Ks = smw + AK_OFF + (kb & 1) * 4608;
        const uint32_t* Vs = smw + AV_OFF + (kb & 1) * 4352;

        float s[16][4];
#pragma unroll
        for (int nt = 0; nt < 16; nt++)
#pragma unroll
            for (int e = 0; e < 4; e++) s[nt][e] = 0.f;
#pragma unroll
        for (int ks = 0; ks < 4; ks++) {
            uint32_t af[4];
            ldm_x4(af, &Qs[(w16 + arow) * 36 + ks * 8 + aword]);
#pragma unroll
            for (int np = 0; np < 8; np++) {
                uint32_t t[4];
                ldm_x4(t, &Ks[(np * 16 + brow) * 36 + ks * 8 + bword]);
                mma_bf16(s[2 * np], af, t);
                mma_bf16(s[2 * np + 1], af, t + 2);
            }
        }

        float rm0 = -1e30f, rm1 = -1e30f;
#pragma unroll
        for (int nt = 0; nt < 16; nt++) {
            rm0 = fmaxf(rm0, fmaxf(s[nt][0], s[nt][1]));
            rm1 = fmaxf(rm1, fmaxf(s[nt][2], s[nt][3]));
        }
        rm0 = fmaxf(rm0, __shfl_xor_sync(0xffffffffu, rm0, 1));
        rm0 = fmaxf(rm0, __shfl_xor_sync(0xffffffffu, rm0, 2));
        rm1 = fmaxf(rm1, __shfl_xor_sync(0xffffffffu, rm1, 1));
        rm1 = fmaxf(rm1, __shfl_xor_sync(0xffffffffu, rm1, 2));
        const float mn0 = fmaxf(m0, rm0), mn1 = fmaxf(m1, rm1);
        const float al0 = ex2f(m0 - mn0), al1 = ex2f(m1 - mn1);
        m0 = mn0; m1 = mn1;
        float sum0 = 0.f, sum1 = 0.f;
#pragma unroll
        for (int nt = 0; nt < 16; nt++) {
            s[nt][0] = ex2f(s[nt][0] - mn0);
            s[nt][1] = ex2f(s[nt][1] - mn0);
            s[nt][2] = ex2f(s[nt][2] - mn1);
            s[nt][3] = ex2f(s[nt][3] - mn1);
            sum0 += s[nt][0] + s[nt][1];
            sum1 += s[nt][2] + s[nt][3];
        }
        sum0 += __shfl_xor_sync(0xffffffffu, sum0, 1);
        sum0 += __shfl_xor_sync(0xffffffffu, sum0, 2);
        sum1 += __shfl_xor_sync(0xffffffffu, sum1, 1);
        sum1 += __shfl_xor_sync(0xffffffffu, sum1, 2);
        l0 = l0 * al0 + sum0;
        l1 = l1 * al1 + sum1;
#pragma unroll
        for (int nt = 0; nt < 8; nt++) {
            o[nt][0] *= al0; o[nt][1] *= al0;
            o[nt][2] *= al1; o[nt][3] *= al1;
        }

#pragma unroll
        for (int i = 0; i < 8; i++) {
            uint32_t af[4];
            af[0] = packbf(s[2 * i][0], s[2 * i][1]);
            af[1] = packbf(s[2 * i][2], s[2 * i][3]);
            af[2] = packbf(s[2 * i + 1][0], s[2 * i + 1][1]);
            af[3] = packbf(s[2 * i + 1][2], s[2 * i + 1][3]);
#pragma unroll
            for (int nvp = 0; nvp < 4; nvp++) {
                uint32_t t[4];
                ldm_x4(t, &Vs[(nvp * 16 + brow) * 68 + i * 8 + bword]);
                mma_bf16(o[2 * nvp], af, t);
                mma_bf16(o[2 * nvp + 1], af, t + 2);
            }
        }
    }

    const float inv0 = 1.f / l0, inv1 = 1.f / l1;
    uint32_t* og = attT + ((size_t)b * NN + qb * 128 + w16 + g) * CCW + h * 32;
    uint32_t* og8 = og + (size_t)8 * CCW;
#pragma unroll
    for (int nv = 0; nv < 8; nv++) {
        og[nv * 4 + tig]  = packbf(o[nv][0] * inv0, o[nv][1] * inv0);
        og8[nv * 4 + tig] = packbf(o[nv][2] * inv1, o[nv][3] * inv1);
    }
}

// ---------------------------------------------------------------------------
extern "C" void kernel_launch(void* const* d_in, const int* in_sizes, int n_in,
                              void* d_out, int out_size) {
    const float* x = (const float*)d_in[0];
    const float* gamma = (const float*)d_in[1];
    const float* beta = (const float*)d_in[2];
    const float* qkv_w = (const float*)d_in[3];
    const float* qkv_b = (const float*)d_in[4];
    const float* proj_w = (const float*)d_in[5];
    const float* proj_b = (const float*)d_in[6];
    float* out = (float*)d_out;

    uint32_t *xnT, *qkT, *vN, *attT, *wq, *wp;
    cudaGetSymbolAddress((void**)&xnT, g_xnT);
    cudaGetSymbolAddress((void**)&qkT, g_qkT);
    cudaGetSymbolAddress((void**)&vN, g_vN);
    cudaGetSymbolAddress((void**)&attT, g_attT);
    cudaGetSymbolAddress((void**)&wq, g_wq);
    cudaGetSymbolAddress((void**)&wp, g_wp);

    // 0. weights -> bf16 (single launch)
    w2bf16_all<<<(CC * CC + 255) / 256, 256>>>((const float4*)qkv_w,
                                               (const float4*)proj_w,
                                               (uint2*)wq, (uint2*)wp);

    // 1. GroupNorm (single global pass) -> packed transposed bf16
    cudaFuncSetAttribute(groupnorm_kernel,
                         cudaFuncAttributeMaxDynamicSharedMemorySize, GN_SMEM);
    groupnorm_kernel<<<BQ * NG, 256, GN_SMEM>>>(x, gamma, beta, xnT);

    // 2. QKV GEMM (CTA 128x256) -> qkT + vN
    cudaFuncSetAttribute(gemm_mma<1>,
                         cudaFuncAttributeMaxDynamicSharedMemorySize, GEMM_SMEM);
    cudaFuncSetAttribute(gemm_mma<0>,
                         cudaFuncAttributeMaxDynamicSharedMemorySize, GEMM_SMEM);
    dim3 gq(NN / 256, (3 * CC) / 128, BQ);
    gemm_mma<1><<<gq, 256, GEMM_SMEM>>>(wq, qkv_b, xnT, nullptr, nullptr,
                                        qkT, vN, 3 * CC);

    // 3. Flash attention -> attT (packed bf16)
    cudaFuncSetAttribute(attn_mma,
                         cudaFuncAttributeMaxDynamicSharedMemorySize, ATTN_SMEM);
    attn_mma<<<dim3(NN / 128, NH, BQ), 256, ATTN_SMEM>>>(qkT, vN, attT);

    // 4. Proj GEMM + residual -> fp32 out
    dim3 gp(NN / 256, CC / 128, BQ);
    gemm_mma<0><<<gp, 256, GEMM_SMEM>>>(wp, proj_b, attT, x, out,
                                        nullptr, nullptr, CC);
}

// round 13
// speedup vs baseline: 1.0523x; 1.0523x over previous
#include <cuda_runtime.h>
#include <cuda_bf16.h>
#include <cstdint>

#define BQ 16
#define CC 512
#define NN 1024
#define NH 8
#define HD 64
#define NG 32
#define CPG 16
#define EPSV 1e-5f
#define CCW 256   // words (bf16x2) per 512-channel row

// ---------------------------------------------------------------------------
// helpers
// ---------------------------------------------------------------------------
__device__ __forceinline__ uint32_t packbf(float lo, float hi) {
    __nv_bfloat162 h = __floats2bfloat162_rn(lo, hi);
    return *reinterpret_cast<uint32_t*>(&h);
}
__device__ __forceinline__ float ex2f(float x) {
    float r;
    asm("ex2.approx.ftz.f32 %0, %1;" : "=f"(r) : "f"(x));
    return r;
}
__device__ __forceinline__ void mma_bf16(float* c, const uint32_t* a,
                                         const uint32_t* b) {
    asm volatile(
        "mma.sync.aligned.m16n8k16.row.col.f32.bf16.bf16.f32 "
        "{%0,%1,%2,%3}, {%4,%5,%6,%7}, {%8,%9}, {%0,%1,%2,%3};"
        : "+f"(c[0]), "+f"(c[1]), "+f"(c[2]), "+f"(c[3])
        : "r"(a[0]), "r"(a[1]), "r"(a[2]), "r"(a[3]), "r"(b[0]), "r"(b[1]));
}
__device__ __forceinline__ void ldm_x4(uint32_t* r, const uint32_t* p) {
    uint32_t a = (uint32_t)__cvta_generic_to_shared(p);
    asm volatile(
        "ldmatrix.sync.aligned.m8n8.x4.shared.b16 {%0,%1,%2,%3}, [%4];"
        : "=r"(r[0]), "=r"(r[1]), "=r"(r[2]), "=r"(r[3]) : "r"(a));
}
__device__ __forceinline__ void cp16(void* sdst, const void* gsrc) {
    uint32_t s = (uint32_t)__cvta_generic_to_shared(sdst);
    asm volatile("cp.async.cg.shared.global [%0], [%1], 16;" :: "r"(s), "l"(gsrc));
}
#define CP_COMMIT() asm volatile("cp.async.commit_group;")
#define CP_WAIT(n) asm volatile("cp.async.wait_group %0;" :: "n"(n))

#define LOG2E 1.44269504f

// ---------------------------------------------------------------------------
// Scratch (bf16x2 words)
// ---------------------------------------------------------------------------
__device__ uint32_t g_xnT[(size_t)BQ * NN * CCW];    // [B,N,C/2]
__device__ uint32_t g_qkT[(size_t)BQ * NN * 2 * CCW];// [B,N, q | k]
__device__ uint32_t g_vN[(size_t)BQ * CC * (NN / 2)];// [B, vch, N/2]
__device__ uint32_t g_attT[(size_t)BQ * NN * CCW];   // [B,N,C/2]
__device__ uint32_t g_wq[(size_t)3 * CC * CCW];      // qkv_w bf16
__device__ uint32_t g_wp[(size_t)CC * CCW];          // proj_w bf16

// ---------------------------------------------------------------------------
// both weights -> bf16 in one launch
// ---------------------------------------------------------------------------
__global__ void w2bf16_all(const float4* __restrict__ qw,
                           const float4* __restrict__ pw,
                           uint2* __restrict__ oq, uint2* __restrict__ op) {
    const int nq = 3 * CC * CC / 4;
    const int np = CC * CC / 4;
    int i = blockIdx.x * 256 + threadIdx.x;
    if (i < nq) {
        float4 v = qw[i];
        oq[i] = make_uint2(packbf(v.x, v.y), packbf(v.z, v.w));
    } else if (i - nq < np) {
        float4 v = pw[i - nq];
        op[i - nq] = make_uint2(packbf(v.x, v.y), packbf(v.z, v.w));
    }
}

// ---------------------------------------------------------------------------
// GroupNorm, single global pass (SMEM-cached group). xnT[b][n][cword].
// ---------------------------------------------------------------------------
#define GN_STRIDE 1028
#define GN_SMEM (16 * GN_STRIDE * 4)

__global__ __launch_bounds__(256) void groupnorm_kernel(
    const float* __restrict__ x, const float* __restrict__ gamma,
    const float* __restrict__ beta, uint32_t* __restrict__ xnT) {
    extern __shared__ float tile[];
    __shared__ float rs[8], rss[8];

    const int b = blockIdx.x / NG;
    const int g = blockIdx.x % NG;
    const float* px = x + ((size_t)b * CC + g * CPG) * NN;
    const int tid = threadIdx.x;
    const int M = CPG * NN;  // 16384

    float s = 0.f, ss = 0.f;
    for (int i = tid; i < M / 4; i += 256) {
        float4 v = ((const float4*)px)[i];
        int c = i >> 8;
        int n4 = (i & 255) * 4;
        *(float4*)&tile[c * GN_STRIDE + n4] = v;
        s += v.x + v.y + v.z + v.w;
        ss += v.x * v.x + v.y * v.y + v.z * v.z + v.w * v.w;
    }
#pragma unroll
    for (int o = 16; o; o >>= 1) {
        s += __shfl_xor_sync(0xffffffffu, s, o);
        ss += __shfl_xor_sync(0xffffffffu, ss, o);
    }
    int wid = tid / 32, lid = tid % 32;
    if (lid == 0) { rs[wid] = s; rss[wid] = ss; }
    __syncthreads();
    if (wid == 0) {
        s = (lid < 8) ? rs[lid] : 0.f;
        ss = (lid < 8) ? rss[lid] : 0.f;
#pragma unroll
        for (int o = 4; o; o >>= 1) {
            s += __shfl_xor_sync(0xffffffffu, s, o);
            ss += __shfl_xor_sync(0xffffffffu, ss, o);
        }
        if (lid == 0) { rs[0] = s; rss[0] = ss; }
    }
    __syncthreads();
    const float mean = rs[0] / (float)M;
    const float var = rss[0] / (float)M - mean * mean;
    const float rstd = rsqrtf(var + EPSV);

    const int cw = tid & 7;
    const float ga0 = gamma[g * CPG + 2 * cw] * rstd;
    const float be0 = beta[g * CPG + 2 * cw];
    const float ga1 = gamma[g * CPG + 2 * cw + 1] * rstd;
    const float be1 = beta[g * CPG + 2 * cw + 1];
    const float* r0 = &tile[(2 * cw) * GN_STRIDE];
    const float* r1 = r0 + GN_STRIDE;
    uint32_t* og = xnT + (size_t)b * NN * CCW + g * 8 + cw;

#pragma unroll
    for (int rep = 0; rep < 32; rep++) {
        int n = rep * 32 + (tid >> 3);
        float v0 = (r0[n] - mean) * ga0 + be0;
        float v1 = (r1[n] - mean) * ga1 + be1;
        og[(size_t)n * CCW] = packbf(v0, v1);
    }
}

// ---------------------------------------------------------------------------
// bf16 mma GEMM (Round-11 config): CTA 128x128, warp 64x32, 3-stage cp.async.
// MODE 0: fp32 out + bias + residual (proj)
// MODE 1: qkv — q/k transposed+packed to qkT (q scaled by 1/8*log2e), v to vN.
// ---------------------------------------------------------------------------
#define BKW 32
#define PADW 36
#define TILE_W (128 * PADW)
#define STAGE_W (2 * TILE_W)
#define GEMM_SMEM (3 * STAGE_W * 4)  // 110592 B

template <int MODE>
__global__ __launch_bounds__(256, 2) void gemm_mma(
    const uint32_t* __restrict__ W, const float* __restrict__ bias,
    const uint32_t* __restrict__ XT, const float* __restrict__ res,
    float* __restrict__ outf, uint32_t* __restrict__ qkT,
    uint32_t* __restrict__ vN, int O) {
    extern __shared__ uint32_t smg[];

    const int tid = threadIdx.x;
    const int wid = tid >> 5, lane = tid & 31;
    const int g = lane >> 2, tig = lane & 3;
    const int wm = wid >> 2, wn = wid & 3;
    const int b = blockIdx.z, n0 = blockIdx.x * 128, m0 = blockIdx.y * 128;

    const int ri = lane & 7, mi = lane >> 3;
    const int arow = (mi & 1) * 8 + ri, aword = (mi >> 1) * 4;
    const int brow = (mi >> 1) * 8 + ri, bword = (mi & 1) * 4;

    const int lr = tid >> 3;
    const int lk = (tid & 7) * 4;

    float acc[4][4][4];
#pragma unroll
    for (int i = 0; i < 4; i++)
#pragma unroll
        for (int j = 0; j < 4; j++)
#pragma unroll
            for (int e = 0; e < 4; e++) acc[i][j][e] = 0.f;

    const uint32_t* Wp = W + (size_t)m0 * CCW;
    const uint32_t* Xp = XT + (size_t)b * NN * CCW + (size_t)n0 * CCW;

    auto issue = [&](int buf, int k0w) {
        uint32_t* As = smg + buf * STAGE_W;
        uint32_t* Bs = As + TILE_W;
#pragma unroll
        for (int p = 0; p < 4; p++) {
            const int r = lr + p * 32;
            cp16(&As[r * PADW + lk], &Wp[(size_t)r * CCW + k0w + lk]);
            cp16(&Bs[r * PADW + lk], &Xp[(size_t)r * CCW + k0w + lk]);
        }
    };

    issue(0, 0); CP_COMMIT();
    issue(1, BKW); CP_COMMIT();

    const int NKT = CCW / BKW;  // 8
    for (int kt = 0; kt < NKT; kt++) {
        CP_WAIT(1);
        __syncthreads();
        if (kt + 2 < NKT) issue((kt + 2) % 3, (kt + 2) * BKW);
        CP_COMMIT();

        const uint32_t* As = smg + (kt % 3) * STAGE_W;
        const uint32_t* Bs = As + TILE_W;
#pragma unroll
        for (int s = 0; s < 4; s++) {  // 4 k16-steps
            uint32_t af[4][4], bf[4][2];
#pragma unroll
            for (int mt = 0; mt < 4; mt++)
                ldm_x4(af[mt],
                       &As[(wm * 64 + mt * 16 + arow) * PADW + s * 8 + aword]);
#pragma unroll
            for (int np = 0; np < 2; np++) {
                uint32_t t[4];
                ldm_x4(t, &Bs[(wn * 32 + np * 16 + brow) * PADW + s * 8 + bword]);
                bf[2 * np][0] = t[0]; bf[2 * np][1] = t[1];
                bf[2 * np + 1][0] = t[2]; bf[2 * np + 1][1] = t[3];
            }
#pragma unroll
            for (int mt = 0; mt < 4; mt++)
#pragma unroll
                for (int nt = 0; nt < 4; nt++)
                    mma_bf16(acc[mt][nt], af[mt], bf[nt]);
        }
    }

    // epilogue
    if (MODE == 0) {
#pragma unroll
        for (int mt = 0; mt < 4; mt++) {
            const int mA = m0 + wm * 64 + mt * 16 + g;
            const float bvA = bias[mA], bvB = bias[mA + 8];
            float* oA = outf + ((size_t)b * O + mA) * NN + n0;
            float* oB = oA + (size_t)8 * NN;
            const float* rA = res + ((size_t)b * O + mA) * NN + n0;
            const float* rB = rA + (size_t)8 * NN;
#pragma unroll
            for (int nt = 0; nt < 4; nt++) {
                const int nc = wn * 32 + nt * 8 + tig * 2;
                float2 ra = *(const float2*)&rA[nc];
                float2 rb = *(const float2*)&rB[nc];
                float2 vA = make_float2(acc[mt][nt][0] + bvA + ra.x,
                                        acc[mt][nt][1] + bvA + ra.y);
                float2 vB = make_float2(acc[mt][nt][2] + bvB + rb.x,
                                        acc[mt][nt][3] + bvB + rb.y);
                *(float2*)&oA[nc] = vA;
                *(float2*)&oB[nc] = vB;
            }
        }
    } else {
        const int region = m0 >> 9;  // 0=q, 1=k, 2=v
        const float sc = (region == 0) ? 0.125f * LOG2E : 1.0f;
#pragma unroll
        for (int mt = 0; mt < 4; mt++) {
            const int mA = m0 + wm * 64 + mt * 16 + g;
            const float bvA = bias[mA], bvB = bias[mA + 8];
#pragma unroll
            for (int nt = 0; nt < 4; nt++) {
                const int nc = n0 + wn * 32 + nt * 8 + tig * 2;
                float v0 = (acc[mt][nt][0] + bvA) * sc;
                float v1 = (acc[mt][nt][1] + bvA) * sc;
                float v2 = (acc[mt][nt][2] + bvB) * sc;
                float v3 = (acc[mt][nt][3] + bvB) * sc;
                if (region < 2) {
                    float p0 = __shfl_down_sync(0xffffffffu, v0, 4);
                    float p1 = __shfl_down_sync(0xffffffffu, v1, 4);
                    float p2 = __shfl_down_sync(0xffffffffu, v2, 4);
                    float p3 = __shfl_down_sync(0xffffffffu, v3, 4);
                    if (!(g & 1)) {
                        const int cw = mA >> 1;
                        size_t base0 = ((size_t)b * NN + nc) * (2 * CCW);
                        size_t base1 = base0 + 2 * CCW;
                        qkT[base0 + cw]     = packbf(v0, p0);
                        qkT[base0 + cw + 4] = packbf(v2, p2);
                        qkT[base1 + cw]     = packbf(v1, p1);
                        qkT[base1 + cw + 4] = packbf(v3, p3);
                    }
                } else {
                    const int ch = mA - 2 * CC;
                    vN[((size_t)b * CC + ch) * (NN / 2) + (nc >> 1)] =
                        packbf(v0, v1);
                    vN[((size_t)b * CC + ch + 8) * (NN / 2) + (nc >> 1)] =
                        packbf(v2, v3);
                }
            }
        }
    }
}

// ---------------------------------------------------------------------------
// Flash attention bf16: Q fragments in registers, ldmatrix K/V,
// double-buffered cp.async K/V, log2-domain softmax.
// SMEM: Qs [128][36], Ks[2][128][36], Vs[2][64][68] = 90112 B, 2 CTAs/SM.
// ---------------------------------------------------------------------------
#define AQ_OFF 0
#define AK_OFF 4608
#define AV_OFF 13824
#define ATTN_SMEM ((13824 + 2 * 4352) * 4)  // 90112 B

__global__ __launch_bounds__(256, 2) void attn_mma(
    const uint32_t* __restrict__ qkT, const uint32_t* __restrict__ vN,
    uint32_t* __restrict__ attT) {
    extern __shared__ uint32_t smw[];
    uint32_t* Qs = smw + AQ_OFF;

    const int qb = blockIdx.x, h = blockIdx.y, b = blockIdx.z;
    const int tid = threadIdx.x, lane = tid & 31;
    const int g = lane >> 2, tig = lane & 3;
    const int w16 = (tid >> 5) * 16;

    const int ri = lane & 7, mi = lane >> 3;
    const int arow = (mi & 1) * 8 + ri, aword = (mi >> 1) * 4;
    const int brow = (mi >> 1) * 8 + ri, bword = (mi & 1) * 4;

    auto issueKV = [&](int buf, int kb) {
        uint32_t* Ks = smw + AK_OFF + buf * 4608;
        uint32_t* Vs = smw + AV_OFF + buf * 4352;
        const uint32_t* kg = qkT + ((size_t)b * NN + kb * 128) * (2 * CCW) +
                             256 + h * 32;
#pragma unroll
        for (int p = 0; p < 4; p++) {
            int idx = p * 256 + tid;
            int n = idx >> 3, q4 = (idx & 7) * 4;
            cp16(&Ks[n * 36 + q4], &kg[(size_t)n * (2 * CCW) + q4]);
        }
        const uint32_t* vg = vN + ((size_t)b * CC + h * 64) * (NN / 2) + kb * 64;
#pragma unroll
        for (int p = 0; p < 4; p++) {
            int idx = p * 256 + tid;
            int dv = idx >> 4, j4 = (idx & 15) * 4;
            cp16(&Vs[dv * 68 + j4], &vg[(size_t)dv * (NN / 2) + j4]);
        }
    };

    // prologue: Q + KV(0) in group 0
    {
        const uint32_t* qg = qkT + ((size_t)b * NN + qb * 128) * (2 * CCW) + h * 32;
#pragma unroll
        for (int p = 0; p < 4; p++) {
            int idx = p * 256 + tid;
            int n = idx >> 3, q4 = (idx & 7) * 4;
            cp16(&Qs[n * 36 + q4], &qg[(size_t)n * (2 * CCW) + q4]);
        }
        issueKV(0, 0);
        CP_COMMIT();
    }

    float m0 = -1e30f, m1 = -1e30f, l0 = 0.f, l1 = 0.f;
    float o[8][4];
#pragma unroll
    for (int nt = 0; nt < 8; nt++)
#pragma unroll
        for (int e = 0; e < 4; e++) o[nt][e] = 0.f;

    uint32_t qf[4][4];  // per-warp Q fragments, all 4 k16-steps (16 regs)

    for (int kb = 0; kb < 8; kb++) {
        __syncthreads();
        if (kb + 1 < 8) {
            issueKV((kb + 1) & 1, kb + 1);
            CP_COMMIT();
            CP_WAIT(1);
        } else {
            CP_WAIT(0);
        }
        __syncthreads();

        if (kb == 0) {  // Q now visible: load fragments once
#pragma unroll
            for (int ks = 0; ks < 4; ks++)
                ldm_x4(qf[ks], &Qs[(w16 + arow) * 36 + ks * 8 + aword]);
        }

        const uint32_t* Ks = smw + AK_OFF + (kb & 1) * 4608;
        const uint32_t* Vs = smw + AV_OFF + (kb & 1) * 4352;

        // S = Q K^T : 4 k16-steps over d=64 (log2-scaled logits)
        float s[16][4];
#pragma unroll
        for (int nt = 0; nt < 16; nt++)
#pragma unroll
            for (int e = 0; e < 4; e++) s[nt][e] = 0.f;
#pragma unroll
        for (int ks = 0; ks < 4; ks++) {
#pragma unroll
            for (int np = 0; np < 8; np++) {
                uint32_t t[4];
                ldm_x4(t, &Ks[(np * 16 + brow) * 36 + ks * 8 + bword]);
                mma_bf16(s[2 * np], qf[ks], t);
                mma_bf16(s[2 * np + 1], qf[ks], t + 2);
            }
        }

        // online softmax in log2 domain
        float rm0 = -1e30f, rm1 = -1e30f;
#pragma unroll
        for (int nt = 0; nt < 16; nt++) {
            rm0 = fmaxf(rm0, fmaxf(s[nt][0], s[nt][1]));
            rm1 = fmaxf(rm1, fmaxf(s[nt][2], s[nt][3]));
        }
        rm0 = fmaxf(rm0, __shfl_xor_sync(0xffffffffu, rm0, 1));
        rm0 = fmaxf(rm0, __shfl_xor_sync(0xffffffffu, rm0, 2));
        rm1 = fmaxf(rm1, __shfl_xor_sync(0xffffffffu, rm1, 1));
        rm1 = fmaxf(rm1, __shfl_xor_sync(0xffffffffu, rm1, 2));
        const float mn0 = fmaxf(m0, rm0), mn1 = fmaxf(m1, rm1);
        const float al0 = ex2f(m0 - mn0), al1 = ex2f(m1 - mn1);
        m0 = mn0; m1 = mn1;
        float sum0 = 0.f, sum1 = 0.f;
#pragma unroll
        for (int nt = 0; nt < 16; nt++) {
            s[nt][0] = ex2f(s[nt][0] - mn0);
            s[nt][1] = ex2f(s[nt][1] - mn0);
            s[nt][2] = ex2f(s[nt][2] - mn1);
            s[nt][3] = ex2f(s[nt][3] - mn1);
            sum0 += s[nt][0] + s[nt][1];
            sum1 += s[nt][2] + s[nt][3];
        }
        sum0 += __shfl_xor_sync(0xffffffffu, sum0, 1);
        sum0 += __shfl_xor_sync(0xffffffffu, sum0, 2);
        sum1 += __shfl_xor_sync(0xffffffffu, sum1, 1);
        sum1 += __shfl_xor_sync(0xffffffffu, sum1, 2);
        l0 = l0 * al0 + sum0;
        l1 = l1 * al1 + sum1;
#pragma unroll
        for (int nt = 0; nt < 8; nt++) {
            o[nt][0] *= al0; o[nt][1] *= al0;
            o[nt][2] *= al1; o[nt][3] *= al1;
        }

        // O += P V^T : P packs straight from C-frags
#pragma unroll
        for (int i = 0; i < 8; i++) {
            uint32_t af[4];
            af[0] = packbf(s[2 * i][0], s[2 * i][1]);
            af[1] = packbf(s[2 * i][2], s[2 * i][3]);
            af[2] = packbf(s[2 * i + 1][0], s[2 * i + 1][1]);
            af[3] = packbf(s[2 * i + 1][2], s[2 * i + 1][3]);
#pragma unroll
            for (int nvp = 0; nvp < 4; nvp++) {
                uint32_t t[4];
                ldm_x4(t, &Vs[(nvp * 16 + brow) * 68 + i * 8 + bword]);
                mma_bf16(o[2 * nvp], af, t);
                mma_bf16(o[2 * nvp + 1], af, t + 2);
            }
        }
    }

    // epilogue: attT[b][n][cword]
    const float inv0 = 1.f / l0, inv1 = 1.f / l1;
    uint32_t* og = attT + ((size_t)b * NN + qb * 128 + w16 + g) * CCW + h * 32;
    uint32_t* og8 = og + (size_t)8 * CCW;
#pragma unroll
    for (int nv = 0; nv < 8; nv++) {
        og[nv * 4 + tig]  = packbf(o[nv][0] * inv0, o[nv][1] * inv0);
        og8[nv * 4 + tig] = packbf(o[nv][2] * inv1, o[nv][3] * inv1);
    }
}

// ---------------------------------------------------------------------------
extern "C" void kernel_launch(void* const* d_in, const int* in_sizes, int n_in,
                              void* d_out, int out_size) {
    const float* x = (const float*)d_in[0];
    const float* gamma = (const float*)d_in[1];
    const float* beta = (const float*)d_in[2];
    const float* qkv_w = (const float*)d_in[3];
    const float* qkv_b = (const float*)d_in[4];
    const float* proj_w = (const float*)d_in[5];
    const float* proj_b = (const float*)d_in[6];
    float* out = (float*)d_out;

    uint32_t *xnT, *qkT, *vN, *attT, *wq, *wp;
    cudaGetSymbolAddress((void**)&xnT, g_xnT);
    cudaGetSymbolAddress((void**)&qkT, g_qkT);
    cudaGetSymbolAddress((void**)&vN, g_vN);
    cudaGetSymbolAddress((void**)&attT, g_attT);
    cudaGetSymbolAddress((void**)&wq, g_wq);
    cudaGetSymbolAddress((void**)&wp, g_wp);

    // 0. weights -> bf16 (single launch)
    w2bf16_all<<<(CC * CC + 255) / 256, 256>>>((const float4*)qkv_w,
                                               (const float4*)proj_w,
                                               (uint2*)wq, (uint2*)wp);

    // 1. GroupNorm (single global pass) -> packed transposed bf16
    cudaFuncSetAttribute(groupnorm_kernel,
                         cudaFuncAttributeMaxDynamicSharedMemorySize, GN_SMEM);
    groupnorm_kernel<<<BQ * NG, 256, GN_SMEM>>>(x, gamma, beta, xnT);

    // 2. QKV GEMM (CTA 128x128) -> qkT + vN
    cudaFuncSetAttribute(gemm_mma<1>,
                         cudaFuncAttributeMaxDynamicSharedMemorySize, GEMM_SMEM);
    cudaFuncSetAttribute(gemm_mma<0>,
                         cudaFuncAttributeMaxDynamicSharedMemorySize, GEMM_SMEM);
    dim3 gq(NN / 128, (3 * CC) / 128, BQ);
    gemm_mma<1><<<gq, 256, GEMM_SMEM>>>(wq, qkv_b, xnT, nullptr, nullptr,
                                        qkT, vN, 3 * CC);

    // 3. Flash attention -> attT (packed bf16)
    cudaFuncSetAttribute(attn_mma,
                         cudaFuncAttributeMaxDynamicSharedMemorySize, ATTN_SMEM);
    attn_mma<<<dim3(NN / 128, NH, BQ), 256, ATTN_SMEM>>>(qkT, vN, attT);

    // 4. Proj GEMM + residual -> fp32 out
    dim3 gp(NN / 128, CC / 128, BQ);
    gemm_mma<0><<<gp, 256, GEMM_SMEM>>>(wp, proj_b, attT, x, out,
                                        nullptr, nullptr, CC);
}

// round 14
// speedup vs baseline: 1.0863x; 1.0323x over previous
#include <cuda_runtime.h>
#include <cuda_bf16.h>
#include <cstdint>

#define BQ 16
#define CC 512
#define NN 1024
#define NH 8
#define HD 64
#define NG 32
#define CPG 16
#define EPSV 1e-5f
#define CCW 256   // words (bf16x2) per 512-channel row

// ---------------------------------------------------------------------------
// helpers
// ---------------------------------------------------------------------------
__device__ __forceinline__ uint32_t packbf(float lo, float hi) {
    __nv_bfloat162 h = __floats2bfloat162_rn(lo, hi);
    return *reinterpret_cast<uint32_t*>(&h);
}
__device__ __forceinline__ float ex2f(float x) {
    float r;
    asm("ex2.approx.ftz.f32 %0, %1;" : "=f"(r) : "f"(x));
    return r;
}
__device__ __forceinline__ void mma_bf16(float* c, const uint32_t* a,
                                         const uint32_t* b) {
    asm volatile(
        "mma.sync.aligned.m16n8k16.row.col.f32.bf16.bf16.f32 "
        "{%0,%1,%2,%3}, {%4,%5,%6,%7}, {%8,%9}, {%0,%1,%2,%3};"
        : "+f"(c[0]), "+f"(c[1]), "+f"(c[2]), "+f"(c[3])
        : "r"(a[0]), "r"(a[1]), "r"(a[2]), "r"(a[3]), "r"(b[0]), "r"(b[1]));
}
__device__ __forceinline__ void ldm_x4(uint32_t* r, const uint32_t* p) {
    uint32_t a = (uint32_t)__cvta_generic_to_shared(p);
    asm volatile(
        "ldmatrix.sync.aligned.m8n8.x4.shared.b16 {%0,%1,%2,%3}, [%4];"
        : "=r"(r[0]), "=r"(r[1]), "=r"(r[2]), "=r"(r[3]) : "r"(a));
}
__device__ __forceinline__ void cp16(void* sdst, const void* gsrc) {
    uint32_t s = (uint32_t)__cvta_generic_to_shared(sdst);
    asm volatile("cp.async.cg.shared.global [%0], [%1], 16;" :: "r"(s), "l"(gsrc));
}
#define CP_COMMIT() asm volatile("cp.async.commit_group;")
#define CP_WAIT(n) asm volatile("cp.async.wait_group %0;" :: "n"(n))

#define LOG2E 1.44269504f

// ---------------------------------------------------------------------------
// Scratch (bf16x2 words)
// ---------------------------------------------------------------------------
__device__ uint32_t g_xnT[(size_t)BQ * NN * CCW];    // [B,N,C/2]
__device__ uint32_t g_qkT[(size_t)BQ * NN * 2 * CCW];// [B,N, q | k]
__device__ uint32_t g_vN[(size_t)BQ * CC * (NN / 2)];// [B, vch, N/2]
__device__ uint32_t g_attT[(size_t)BQ * NN * CCW];   // [B,N,C/2]
__device__ uint32_t g_wq[(size_t)3 * CC * CCW];      // qkv_w bf16
__device__ uint32_t g_wp[(size_t)CC * CCW];          // proj_w bf16

// ---------------------------------------------------------------------------
// Fused GroupNorm + weight conversion.
// Blocks [0, 512): GroupNorm single-pass (SMEM-cached group) -> xnT.
// Blocks [512, ...): qkv_w/proj_w fp32 -> bf16 pack.
// ---------------------------------------------------------------------------
#define GN_STRIDE 1028
#define GN_SMEM (16 * GN_STRIDE * 4)
#define GN_BLOCKS (BQ * NG)                       // 512
#define W4_QKV (3 * CC * CC / 4)                  // 196608 float4
#define W4_ALL (W4_QKV + CC * CC / 4)             // 262144 float4
#define W_BLOCKS ((W4_ALL + 255) / 256)           // 1024

__global__ __launch_bounds__(256) void gn_w2_kernel(
    const float* __restrict__ x, const float* __restrict__ gamma,
    const float* __restrict__ beta, uint32_t* __restrict__ xnT,
    const float4* __restrict__ qw, const float4* __restrict__ pw,
    uint2* __restrict__ oq, uint2* __restrict__ op) {
    const int tid = threadIdx.x;

    if (blockIdx.x >= GN_BLOCKS) {
        int i = (blockIdx.x - GN_BLOCKS) * 256 + tid;
        if (i < W4_QKV) {
            float4 v = qw[i];
            oq[i] = make_uint2(packbf(v.x, v.y), packbf(v.z, v.w));
        } else if (i < W4_ALL) {
            float4 v = pw[i - W4_QKV];
            op[i - W4_QKV] = make_uint2(packbf(v.x, v.y), packbf(v.z, v.w));
        }
        return;
    }

    extern __shared__ float tile[];
    __shared__ float rs[8], rss[8];

    const int b = blockIdx.x / NG;
    const int g = blockIdx.x % NG;
    const float* px = x + ((size_t)b * CC + g * CPG) * NN;
    const int M = CPG * NN;  // 16384

    float s = 0.f, ss = 0.f;
    for (int i = tid; i < M / 4; i += 256) {
        float4 v = ((const float4*)px)[i];
        int c = i >> 8;
        int n4 = (i & 255) * 4;
        *(float4*)&tile[c * GN_STRIDE + n4] = v;
        s += v.x + v.y + v.z + v.w;
        ss += v.x * v.x + v.y * v.y + v.z * v.z + v.w * v.w;
    }
#pragma unroll
    for (int o = 16; o; o >>= 1) {
        s += __shfl_xor_sync(0xffffffffu, s, o);
        ss += __shfl_xor_sync(0xffffffffu, ss, o);
    }
    int wid = tid / 32, lid = tid % 32;
    if (lid == 0) { rs[wid] = s; rss[wid] = ss; }
    __syncthreads();
    if (wid == 0) {
        s = (lid < 8) ? rs[lid] : 0.f;
        ss = (lid < 8) ? rss[lid] : 0.f;
#pragma unroll
        for (int o = 4; o; o >>= 1) {
            s += __shfl_xor_sync(0xffffffffu, s, o);
            ss += __shfl_xor_sync(0xffffffffu, ss, o);
        }
        if (lid == 0) { rs[0] = s; rss[0] = ss; }
    }
    __syncthreads();
    const float mean = rs[0] / (float)M;
    const float var = rss[0] / (float)M - mean * mean;
    const float rstd = rsqrtf(var + EPSV);

    const int cw = tid & 7;
    const float ga0 = gamma[g * CPG + 2 * cw] * rstd;
    const float be0 = beta[g * CPG + 2 * cw];
    const float ga1 = gamma[g * CPG + 2 * cw + 1] * rstd;
    const float be1 = beta[g * CPG + 2 * cw + 1];
    const float* r0 = &tile[(2 * cw) * GN_STRIDE];
    const float* r1 = r0 + GN_STRIDE;
    uint32_t* og = xnT + (size_t)b * NN * CCW + g * 8 + cw;

#pragma unroll
    for (int rep = 0; rep < 32; rep++) {
        int n = rep * 32 + (tid >> 3);
        float v0 = (r0[n] - mean) * ga0 + be0;
        float v1 = (r1[n] - mean) * ga1 + be1;
        og[(size_t)n * CCW] = packbf(v0, v1);
    }
}

// ---------------------------------------------------------------------------
// bf16 mma GEMM (proven config): CTA 128x128, warp 64x32, 3-stage cp.async.
// MODE 0: fp32 out + bias + residual (proj)
// MODE 1: qkv — q/k transposed+packed to qkT (q scaled by 1/8*log2e), v to vN.
// ---------------------------------------------------------------------------
#define BKW 32
#define PADW 36
#define TILE_W (128 * PADW)
#define STAGE_W (2 * TILE_W)
#define GEMM_SMEM (3 * STAGE_W * 4)  // 110592 B

template <int MODE>
__global__ __launch_bounds__(256, 2) void gemm_mma(
    const uint32_t* __restrict__ W, const float* __restrict__ bias,
    const uint32_t* __restrict__ XT, const float* __restrict__ res,
    float* __restrict__ outf, uint32_t* __restrict__ qkT,
    uint32_t* __restrict__ vN, int O) {
    extern __shared__ uint32_t smg[];

    const int tid = threadIdx.x;
    const int wid = tid >> 5, lane = tid & 31;
    const int g = lane >> 2, tig = lane & 3;
    const int wm = wid >> 2, wn = wid & 3;
    const int b = blockIdx.z, n0 = blockIdx.x * 128, m0 = blockIdx.y * 128;

    const int ri = lane & 7, mi = lane >> 3;
    const int arow = (mi & 1) * 8 + ri, aword = (mi >> 1) * 4;
    const int brow = (mi >> 1) * 8 + ri, bword = (mi & 1) * 4;

    const int lr = tid >> 3;
    const int lk = (tid & 7) * 4;

    float acc[4][4][4];
#pragma unroll
    for (int i = 0; i < 4; i++)
#pragma unroll
        for (int j = 0; j < 4; j++)
#pragma unroll
            for (int e = 0; e < 4; e++) acc[i][j][e] = 0.f;

    const uint32_t* Wp = W + (size_t)m0 * CCW;
    const uint32_t* Xp = XT + (size_t)b * NN * CCW + (size_t)n0 * CCW;

    auto issue = [&](int buf, int k0w) {
        uint32_t* As = smg + buf * STAGE_W;
        uint32_t* Bs = As + TILE_W;
#pragma unroll
        for (int p = 0; p < 4; p++) {
            const int r = lr + p * 32;
            cp16(&As[r * PADW + lk], &Wp[(size_t)r * CCW + k0w + lk]);
            cp16(&Bs[r * PADW + lk], &Xp[(size_t)r * CCW + k0w + lk]);
        }
    };

    issue(0, 0); CP_COMMIT();
    issue(1, BKW); CP_COMMIT();

    const int NKT = CCW / BKW;  // 8
    for (int kt = 0; kt < NKT; kt++) {
        CP_WAIT(1);
        __syncthreads();
        if (kt + 2 < NKT) issue((kt + 2) % 3, (kt + 2) * BKW);
        CP_COMMIT();

        const uint32_t* As = smg + (kt % 3) * STAGE_W;
        const uint32_t* Bs = As + TILE_W;
#pragma unroll
        for (int s = 0; s < 4; s++) {  // 4 k16-steps
            uint32_t af[4][4], bf[4][2];
#pragma unroll
            for (int mt = 0; mt < 4; mt++)
                ldm_x4(af[mt],
                       &As[(wm * 64 + mt * 16 + arow) * PADW + s * 8 + aword]);
#pragma unroll
            for (int np = 0; np < 2; np++) {
                uint32_t t[4];
                ldm_x4(t, &Bs[(wn * 32 + np * 16 + brow) * PADW + s * 8 + bword]);
                bf[2 * np][0] = t[0]; bf[2 * np][1] = t[1];
                bf[2 * np + 1][0] = t[2]; bf[2 * np + 1][1] = t[3];
            }
#pragma unroll
            for (int mt = 0; mt < 4; mt++)
#pragma unroll
                for (int nt = 0; nt < 4; nt++)
                    mma_bf16(acc[mt][nt], af[mt], bf[nt]);
        }
    }

    // epilogue
    if (MODE == 0) {
#pragma unroll
        for (int mt = 0; mt < 4; mt++) {
            const int mA = m0 + wm * 64 + mt * 16 + g;
            const float bvA = bias[mA], bvB = bias[mA + 8];
            float* oA = outf + ((size_t)b * O + mA) * NN + n0;
            float* oB = oA + (size_t)8 * NN;
            const float* rA = res + ((size_t)b * O + mA) * NN + n0;
            const float* rB = rA + (size_t)8 * NN;
#pragma unroll
            for (int nt = 0; nt < 4; nt++) {
                const int nc = wn * 32 + nt * 8 + tig * 2;
                float2 ra = *(const float2*)&rA[nc];
                float2 rb = *(const float2*)&rB[nc];
                float2 vA = make_float2(acc[mt][nt][0] + bvA + ra.x,
                                        acc[mt][nt][1] + bvA + ra.y);
                float2 vB = make_float2(acc[mt][nt][2] + bvB + rb.x,
                                        acc[mt][nt][3] + bvB + rb.y);
                *(float2*)&oA[nc] = vA;
                *(float2*)&oB[nc] = vB;
            }
        }
    } else {
        const int region = m0 >> 9;  // 0=q, 1=k, 2=v
        const float sc = (region == 0) ? 0.125f * LOG2E : 1.0f;
#pragma unroll
        for (int mt = 0; mt < 4; mt++) {
            const int mA = m0 + wm * 64 + mt * 16 + g;
            const float bvA = bias[mA], bvB = bias[mA + 8];
#pragma unroll
            for (int nt = 0; nt < 4; nt++) {
                const int nc = n0 + wn * 32 + nt * 8 + tig * 2;
                float v0 = (acc[mt][nt][0] + bvA) * sc;
                float v1 = (acc[mt][nt][1] + bvA) * sc;
                float v2 = (acc[mt][nt][2] + bvB) * sc;
                float v3 = (acc[mt][nt][3] + bvB) * sc;
                if (region < 2) {
                    float p0 = __shfl_down_sync(0xffffffffu, v0, 4);
                    float p1 = __shfl_down_sync(0xffffffffu, v1, 4);
                    float p2 = __shfl_down_sync(0xffffffffu, v2, 4);
                    float p3 = __shfl_down_sync(0xffffffffu, v3, 4);
                    if (!(g & 1)) {
                        const int cw = mA >> 1;
                        size_t base0 = ((size_t)b * NN + nc) * (2 * CCW);
                        size_t base1 = base0 + 2 * CCW;
                        qkT[base0 + cw]     = packbf(v0, p0);
                        qkT[base0 + cw + 4] = packbf(v2, p2);
                        qkT[base1 + cw]     = packbf(v1, p1);
                        qkT[base1 + cw + 4] = packbf(v3, p3);
                    }
                } else {
                    const int ch = mA - 2 * CC;
                    vN[((size_t)b * CC + ch) * (NN / 2) + (nc >> 1)] =
                        packbf(v0, v1);
                    vN[((size_t)b * CC + ch + 8) * (NN / 2) + (nc >> 1)] =
                        packbf(v2, v3);
                }
            }
        }
    }
}

// ---------------------------------------------------------------------------
// Flash attention bf16 (R11 proven config): ldmatrix Q/K/V, double-buffered
// cp.async K/V, log2-domain softmax (q pre-scaled by 1/8*log2e).
// SMEM: Qs [128][36], Ks[2][128][36], Vs[2][64][68] = 90112 B, 2 CTAs/SM.
// ---------------------------------------------------------------------------
#define AQ_OFF 0
#define AK_OFF 4608
#define AV_OFF 13824
#define ATTN_SMEM ((13824 + 2 * 4352) * 4)  // 90112 B

__global__ __launch_bounds__(256, 2) void attn_mma(
    const uint32_t* __restrict__ qkT, const uint32_t* __restrict__ vN,
    uint32_t* __restrict__ attT) {
    extern __shared__ uint32_t smw[];
    uint32_t* Qs = smw + AQ_OFF;

    const int qb = blockIdx.x, h = blockIdx.y, b = blockIdx.z;
    const int tid = threadIdx.x, lane = tid & 31;
    const int g = lane >> 2, tig = lane & 3;
    const int w16 = (tid >> 5) * 16;

    const int ri = lane & 7, mi = lane >> 3;
    const int arow = (mi & 1) * 8 + ri, aword = (mi >> 1) * 4;
    const int brow = (mi >> 1) * 8 + ri, bword = (mi & 1) * 4;

    auto issueKV = [&](int buf, int kb) {
        uint32_t* Ks = smw + AK_OFF + buf * 4608;
        uint32_t* Vs = smw + AV_OFF + buf * 4352;
        const uint32_t* kg = qkT + ((size_t)b * NN + kb * 128) * (2 * CCW) +
                             256 + h * 32;
#pragma unroll
        for (int p = 0; p < 4; p++) {
            int idx = p * 256 + tid;
            int n = idx >> 3, q4 = (idx & 7) * 4;
            cp16(&Ks[n * 36 + q4], &kg[(size_t)n * (2 * CCW) + q4]);
        }
        const uint32_t* vg = vN + ((size_t)b * CC + h * 64) * (NN / 2) + kb * 64;
#pragma unroll
        for (int p = 0; p < 4; p++) {
            int idx = p * 256 + tid;
            int dv = idx >> 4, j4 = (idx & 15) * 4;
            cp16(&Vs[dv * 68 + j4], &vg[(size_t)dv * (NN / 2) + j4]);
        }
    };

    // prologue: Q + KV(0) in group 0
    {
        const uint32_t* qg = qkT + ((size_t)b * NN + qb * 128) * (2 * CCW) + h * 32;
#pragma unroll
        for (int p = 0; p < 4; p++) {
            int idx = p * 256 + tid;
            int n = idx >> 3, q4 = (idx & 7) * 4;
            cp16(&Qs[n * 36 + q4], &qg[(size_t)n * (2 * CCW) + q4]);
        }
        issueKV(0, 0);
        CP_COMMIT();
    }

    float m0 = -1e30f, m1 = -1e30f, l0 = 0.f, l1 = 0.f;
    float o[8][4];
#pragma unroll
    for (int nt = 0; nt < 8; nt++)
#pragma unroll
        for (int e = 0; e < 4; e++) o[nt][e] = 0.f;

    for (int kb = 0; kb < 8; kb++) {
        __syncthreads();
        if (kb + 1 < 8) {
            issueKV((kb + 1) & 1, kb + 1);
            CP_COMMIT();
            CP_WAIT(1);
        } else {
            CP_WAIT(0);
        }
        __syncthreads();

        const uint32_t* Ks = smw + AK_OFF + (kb & 1) * 4608;
        const uint32_t* Vs = smw + AV_OFF + (kb & 1) * 4352;

        // S = Q K^T : 4 k16-steps over d=64 (log2-scaled logits)
        float s[16][4];
#pragma unroll
        for (int nt = 0; nt < 16; nt++)
#pragma unroll
            for (int e = 0; e < 4; e++) s[nt][e] = 0.f;
#pragma unroll
        for (int ks = 0; ks < 4; ks++) {
            uint32_t af[4];
            ldm_x4(af, &Qs[(w16 + arow) * 36 + ks * 8 + aword]);
#pragma unroll
            for (int np = 0; np < 8; np++) {
                uint32_t t[4];
                ldm_x4(t, &Ks[(np * 16 + brow) * 36 + ks * 8 + bword]);
                mma_bf16(s[2 * np], af, t);
                mma_bf16(s[2 * np + 1], af, t + 2);
            }
        }

        // online softmax in log2 domain (rows g / g+8, quad shfl)
        float rm0 = -1e30f, rm1 = -1e30f;
#pragma unroll
        for (int nt = 0; nt < 16; nt++) {
            rm0 = fmaxf(rm0, fmaxf(s[nt][0], s[nt][1]));
            rm1 = fmaxf(rm1, fmaxf(s[nt][2], s[nt][3]));
        }
        rm0 = fmaxf(rm0, __shfl_xor_sync(0xffffffffu, rm0, 1));
        rm0 = fmaxf(rm0, __shfl_xor_sync(0xffffffffu, rm0, 2));
        rm1 = fmaxf(rm1, __shfl_xor_sync(0xffffffffu, rm1, 1));
        rm1 = fmaxf(rm1, __shfl_xor_sync(0xffffffffu, rm1, 2));
        const float mn0 = fmaxf(m0, rm0), mn1 = fmaxf(m1, rm1);
        const float al0 = ex2f(m0 - mn0), al1 = ex2f(m1 - mn1);
        m0 = mn0; m1 = mn1;
        float sum0 = 0.f, sum1 = 0.f;
#pragma unroll
        for (int nt = 0; nt < 16; nt++) {
            s[nt][0] = ex2f(s[nt][0] - mn0);
            s[nt][1] = ex2f(s[nt][1] - mn0);
            s[nt][2] = ex2f(s[nt][2] - mn1);
            s[nt][3] = ex2f(s[nt][3] - mn1);
            sum0 += s[nt][0] + s[nt][1];
            sum1 += s[nt][2] + s[nt][3];
        }
        sum0 += __shfl_xor_sync(0xffffffffu, sum0, 1);
        sum0 += __shfl_xor_sync(0xffffffffu, sum0, 2);
        sum1 += __shfl_xor_sync(0xffffffffu, sum1, 1);
        sum1 += __shfl_xor_sync(0xffffffffu, sum1, 2);
        l0 = l0 * al0 + sum0;
        l1 = l1 * al1 + sum1;
#pragma unroll
        for (int nt = 0; nt < 8; nt++) {
            o[nt][0] *= al0; o[nt][1] *= al0;
            o[nt][2] *= al1; o[nt][3] *= al1;
        }

        // O += P V^T : P packs straight from C-frags
#pragma unroll
        for (int i = 0; i < 8; i++) {
            uint32_t af[4];
            af[0] = packbf(s[2 * i][0], s[2 * i][1]);
            af[1] = packbf(s[2 * i][2], s[2 * i][3]);
            af[2] = packbf(s[2 * i + 1][0], s[2 * i + 1][1]);
            af[3] = packbf(s[2 * i + 1][2], s[2 * i + 1][3]);
#pragma unroll
            for (int nvp = 0; nvp < 4; nvp++) {
                uint32_t t[4];
                ldm_x4(t, &Vs[(nvp * 16 + brow) * 68 + i * 8 + bword]);
                mma_bf16(o[2 * nvp], af, t);
                mma_bf16(o[2 * nvp + 1], af, t + 2);
            }
        }
    }

    // epilogue: attT[b][n][cword]
    const float inv0 = 1.f / l0, inv1 = 1.f / l1;
    uint32_t* og = attT + ((size_t)b * NN + qb * 128 + w16 + g) * CCW + h * 32;
    uint32_t* og8 = og + (size_t)8 * CCW;
#pragma unroll
    for (int nv = 0; nv < 8; nv++) {
        og[nv * 4 + tig]  = packbf(o[nv][0] * inv0, o[nv][1] * inv0);
        og8[nv * 4 + tig] = packbf(o[nv][2] * inv1, o[nv][3] * inv1);
    }
}

// ---------------------------------------------------------------------------
extern "C" void kernel_launch(void* const* d_in, const int* in_sizes, int n_in,
                              void* d_out, int out_size) {
    const float* x = (const float*)d_in[0];
    const float* gamma = (const float*)d_in[1];
    const float* beta = (const float*)d_in[2];
    const float* qkv_w = (const float*)d_in[3];
    const float* qkv_b = (const float*)d_in[4];
    const float* proj_w = (const float*)d_in[5];
    const float* proj_b = (const float*)d_in[6];
    float* out = (float*)d_out;

    uint32_t *xnT, *qkT, *vN, *attT, *wq, *wp;
    cudaGetSymbolAddress((void**)&xnT, g_xnT);
    cudaGetSymbolAddress((void**)&qkT, g_qkT);
    cudaGetSymbolAddress((void**)&vN, g_vN);
    cudaGetSymbolAddress((void**)&attT, g_attT);
    cudaGetSymbolAddress((void**)&wq, g_wq);
    cudaGetSymbolAddress((void**)&wp, g_wp);

    // 1. Fused GroupNorm + weight->bf16 conversion (one launch)
    cudaFuncSetAttribute(gn_w2_kernel,
                         cudaFuncAttributeMaxDynamicSharedMemorySize, GN_SMEM);
    gn_w2_kernel<<<GN_BLOCKS + W_BLOCKS, 256, GN_SMEM>>>(
        x, gamma, beta, xnT, (const float4*)qkv_w, (const float4*)proj_w,
        (uint2*)wq, (uint2*)wp);

    // 2. QKV GEMM (CTA 128x128) -> qkT + vN
    cudaFuncSetAttribute(gemm_mma<1>,
                         cudaFuncAttributeMaxDynamicSharedMemorySize, GEMM_SMEM);
    cudaFuncSetAttribute(gemm_mma<0>,
                         cudaFuncAttributeMaxDynamicSharedMemorySize, GEMM_SMEM);
    dim3 gq(NN / 128, (3 * CC) / 128, BQ);
    gemm_mma<1><<<gq, 256, GEMM_SMEM>>>(wq, qkv_b, xnT, nullptr, nullptr,
                                        qkT, vN, 3 * CC);

    // 3. Flash attention -> attT (packed bf16)
    cudaFuncSetAttribute(attn_mma,
                         cudaFuncAttributeMaxDynamicSharedMemorySize, ATTN_SMEM);
    attn_mma<<<dim3(NN / 128, NH, BQ), 256, ATTN_SMEM>>>(qkT, vN, attT);

    // 4. Proj GEMM + residual -> fp32 out
    dim3 gp(NN / 128, CC / 128, BQ);
    gemm_mma<0><<<gp, 256, GEMM_SMEM>>>(wp, proj_b, attT, x, out,
                                        nullptr, nullptr, CC);
}

// round 15
// speedup vs baseline: 1.0964x; 1.0093x over previous
#include <cuda_runtime.h>
#include <cuda_bf16.h>
#include <cstdint>

#define BQ 16
#define CC 512
#define NN 1024
#define NH 8
#define HD 64
#define NG 32
#define CPG 16
#define EPSV 1e-5f
#define CCW 256   // words (bf16x2) per 512-channel row

// ---------------------------------------------------------------------------
// helpers
// ---------------------------------------------------------------------------
__device__ __forceinline__ uint32_t packbf(float lo, float hi) {
    __nv_bfloat162 h = __floats2bfloat162_rn(lo, hi);
    return *reinterpret_cast<uint32_t*>(&h);
}
__device__ __forceinline__ float ex2f(float x) {
    float r;
    asm("ex2.approx.ftz.f32 %0, %1;" : "=f"(r) : "f"(x));
    return r;
}
__device__ __forceinline__ void mma_bf16(float* c, const uint32_t* a,
                                         const uint32_t* b) {
    asm volatile(
        "mma.sync.aligned.m16n8k16.row.col.f32.bf16.bf16.f32 "
        "{%0,%1,%2,%3}, {%4,%5,%6,%7}, {%8,%9}, {%0,%1,%2,%3};"
        : "+f"(c[0]), "+f"(c[1]), "+f"(c[2]), "+f"(c[3])
        : "r"(a[0]), "r"(a[1]), "r"(a[2]), "r"(a[3]), "r"(b[0]), "r"(b[1]));
}
__device__ __forceinline__ void ldm_x4(uint32_t* r, const uint32_t* p) {
    uint32_t a = (uint32_t)__cvta_generic_to_shared(p);
    asm volatile(
        "ldmatrix.sync.aligned.m8n8.x4.shared.b16 {%0,%1,%2,%3}, [%4];"
        : "=r"(r[0]), "=r"(r[1]), "=r"(r[2]), "=r"(r[3]) : "r"(a));
}
__device__ __forceinline__ void cp16(void* sdst, const void* gsrc) {
    uint32_t s = (uint32_t)__cvta_generic_to_shared(sdst);
    asm volatile("cp.async.cg.shared.global [%0], [%1], 16;" :: "r"(s), "l"(gsrc));
}
#define CP_COMMIT() asm volatile("cp.async.commit_group;")
#define CP_WAIT(n) asm volatile("cp.async.wait_group %0;" :: "n"(n))

#define LOG2E 1.44269504f

// ---------------------------------------------------------------------------
// Scratch (bf16x2 words)
// ---------------------------------------------------------------------------
__device__ uint32_t g_xnT[(size_t)BQ * NN * CCW];    // [B,N,C/2]
__device__ uint32_t g_qkT[(size_t)BQ * NN * 2 * CCW];// [B,N, q | k]
__device__ uint32_t g_vN[(size_t)BQ * CC * (NN / 2)];// [B, vch, N/2]
__device__ uint32_t g_attT[(size_t)BQ * NN * CCW];   // [B,N,C/2]
__device__ uint32_t g_wq[(size_t)3 * CC * CCW];      // qkv_w bf16
__device__ uint32_t g_wp[(size_t)CC * CCW];          // proj_w bf16

// ---------------------------------------------------------------------------
// Fused GroupNorm + weight conversion.
// Blocks [0, 512): GroupNorm single-pass (SMEM-cached group) -> xnT.
// Blocks [512, ...): qkv_w/proj_w fp32 -> bf16 pack.
// ---------------------------------------------------------------------------
#define GN_STRIDE 1028
#define GN_SMEM (16 * GN_STRIDE * 4)
#define GN_BLOCKS (BQ * NG)                       // 512
#define W4_QKV (3 * CC * CC / 4)                  // 196608 float4
#define W4_ALL (W4_QKV + CC * CC / 4)             // 262144 float4
#define W_BLOCKS ((W4_ALL + 255) / 256)           // 1024

__global__ __launch_bounds__(256) void gn_w2_kernel(
    const float* __restrict__ x, const float* __restrict__ gamma,
    const float* __restrict__ beta, uint32_t* __restrict__ xnT,
    const float4* __restrict__ qw, const float4* __restrict__ pw,
    uint2* __restrict__ oq, uint2* __restrict__ op) {
    const int tid = threadIdx.x;

    if (blockIdx.x >= GN_BLOCKS) {
        int i = (blockIdx.x - GN_BLOCKS) * 256 + tid;
        if (i < W4_QKV) {
            float4 v = qw[i];
            oq[i] = make_uint2(packbf(v.x, v.y), packbf(v.z, v.w));
        } else if (i < W4_ALL) {
            float4 v = pw[i - W4_QKV];
            op[i - W4_QKV] = make_uint2(packbf(v.x, v.y), packbf(v.z, v.w));
        }
        return;
    }

    extern __shared__ float tile[];
    __shared__ float rs[8], rss[8];

    const int b = blockIdx.x / NG;
    const int g = blockIdx.x % NG;
    const float* px = x + ((size_t)b * CC + g * CPG) * NN;
    const int M = CPG * NN;  // 16384

    float s = 0.f, ss = 0.f;
    for (int i = tid; i < M / 4; i += 256) {
        float4 v = ((const float4*)px)[i];
        int c = i >> 8;
        int n4 = (i & 255) * 4;
        *(float4*)&tile[c * GN_STRIDE + n4] = v;
        s += v.x + v.y + v.z + v.w;
        ss += v.x * v.x + v.y * v.y + v.z * v.z + v.w * v.w;
    }
#pragma unroll
    for (int o = 16; o; o >>= 1) {
        s += __shfl_xor_sync(0xffffffffu, s, o);
        ss += __shfl_xor_sync(0xffffffffu, ss, o);
    }
    int wid = tid / 32, lid = tid % 32;
    if (lid == 0) { rs[wid] = s; rss[wid] = ss; }
    __syncthreads();
    if (wid == 0) {
        s = (lid < 8) ? rs[lid] : 0.f;
        ss = (lid < 8) ? rss[lid] : 0.f;
#pragma unroll
        for (int o = 4; o; o >>= 1) {
            s += __shfl_xor_sync(0xffffffffu, s, o);
            ss += __shfl_xor_sync(0xffffffffu, ss, o);
        }
        if (lid == 0) { rs[0] = s; rss[0] = ss; }
    }
    __syncthreads();
    const float mean = rs[0] / (float)M;
    const float var = rss[0] / (float)M - mean * mean;
    const float rstd = rsqrtf(var + EPSV);

    const int cw = tid & 7;
    const float ga0 = gamma[g * CPG + 2 * cw] * rstd;
    const float be0 = beta[g * CPG + 2 * cw];
    const float ga1 = gamma[g * CPG + 2 * cw + 1] * rstd;
    const float be1 = beta[g * CPG + 2 * cw + 1];
    const float* r0 = &tile[(2 * cw) * GN_STRIDE];
    const float* r1 = r0 + GN_STRIDE;
    uint32_t* og = xnT + (size_t)b * NN * CCW + g * 8 + cw;

#pragma unroll
    for (int rep = 0; rep < 32; rep++) {
        int n = rep * 32 + (tid >> 3);
        float v0 = (r0[n] - mean) * ga0 + be0;
        float v1 = (r1[n] - mean) * ga1 + be1;
        og[(size_t)n * CCW] = packbf(v0, v1);
    }
}

// ---------------------------------------------------------------------------
// bf16 mma GEMM: CTA 128x128, warp 64x32, 3-stage cp.async, BK=64.
// Residual/bias folded into accumulator INIT (overlaps pipeline ramp).
// MODE 0: acc = res + bias; epilogue = pure fp32 stores (proj).
// MODE 1: acc = bias; epilogue packs q/k transposed to qkT (q scaled), v to vN.
// ---------------------------------------------------------------------------
#define BKW 32
#define PADW 36
#define TILE_W (128 * PADW)
#define STAGE_W (2 * TILE_W)
#define GEMM_SMEM (3 * STAGE_W * 4)  // 110592 B

template <int MODE>
__global__ __launch_bounds__(256, 2) void gemm_mma(
    const uint32_t* __restrict__ W, const float* __restrict__ bias,
    const uint32_t* __restrict__ XT, const float* __restrict__ res,
    float* __restrict__ outf, uint32_t* __restrict__ qkT,
    uint32_t* __restrict__ vN, int O) {
    extern __shared__ uint32_t smg[];

    const int tid = threadIdx.x;
    const int wid = tid >> 5, lane = tid & 31;
    const int g = lane >> 2, tig = lane & 3;
    const int wm = wid >> 2, wn = wid & 3;
    const int b = blockIdx.z, n0 = blockIdx.x * 128, m0 = blockIdx.y * 128;

    const int ri = lane & 7, mi = lane >> 3;
    const int arow = (mi & 1) * 8 + ri, aword = (mi >> 1) * 4;
    const int brow = (mi >> 1) * 8 + ri, bword = (mi & 1) * 4;

    const int lr = tid >> 3;
    const int lk = (tid & 7) * 4;

    const uint32_t* Wp = W + (size_t)m0 * CCW;
    const uint32_t* Xp = XT + (size_t)b * NN * CCW + (size_t)n0 * CCW;

    auto issue = [&](int buf, int k0w) {
        uint32_t* As = smg + buf * STAGE_W;
        uint32_t* Bs = As + TILE_W;
#pragma unroll
        for (int p = 0; p < 4; p++) {
            const int r = lr + p * 32;
            cp16(&As[r * PADW + lk], &Wp[(size_t)r * CCW + k0w + lk]);
            cp16(&Bs[r * PADW + lk], &Xp[(size_t)r * CCW + k0w + lk]);
        }
    };

    issue(0, 0); CP_COMMIT();
    issue(1, BKW); CP_COMMIT();

    // accumulator init: bias (+ residual for MODE 0); LDGs overlap cp.async ramp
    float acc[4][4][4];
#pragma unroll
    for (int mt = 0; mt < 4; mt++) {
        const int mA = m0 + wm * 64 + mt * 16 + g;
        const float bvA = bias[mA], bvB = bias[mA + 8];
#pragma unroll
        for (int nt = 0; nt < 4; nt++) {
            if (MODE == 0) {
                const int nc = wn * 32 + nt * 8 + tig * 2;
                const float* rA = res + ((size_t)b * O + mA) * NN + n0 + nc;
                const float* rB = rA + (size_t)8 * NN;
                float2 ra = *(const float2*)rA;
                float2 rb = *(const float2*)rB;
                acc[mt][nt][0] = bvA + ra.x;
                acc[mt][nt][1] = bvA + ra.y;
                acc[mt][nt][2] = bvB + rb.x;
                acc[mt][nt][3] = bvB + rb.y;
            } else {
                acc[mt][nt][0] = bvA;
                acc[mt][nt][1] = bvA;
                acc[mt][nt][2] = bvB;
                acc[mt][nt][3] = bvB;
            }
        }
    }

    const int NKT = CCW / BKW;  // 8
    for (int kt = 0; kt < NKT; kt++) {
        CP_WAIT(1);
        __syncthreads();
        if (kt + 2 < NKT) issue((kt + 2) % 3, (kt + 2) * BKW);
        CP_COMMIT();

        const uint32_t* As = smg + (kt % 3) * STAGE_W;
        const uint32_t* Bs = As + TILE_W;
#pragma unroll
        for (int s = 0; s < 4; s++) {  // 4 k16-steps
            uint32_t af[4][4], bf[4][2];
#pragma unroll
            for (int mt = 0; mt < 4; mt++)
                ldm_x4(af[mt],
                       &As[(wm * 64 + mt * 16 + arow) * PADW + s * 8 + aword]);
#pragma unroll
            for (int np = 0; np < 2; np++) {
                uint32_t t[4];
                ldm_x4(t, &Bs[(wn * 32 + np * 16 + brow) * PADW + s * 8 + bword]);
                bf[2 * np][0] = t[0]; bf[2 * np][1] = t[1];
                bf[2 * np + 1][0] = t[2]; bf[2 * np + 1][1] = t[3];
            }
#pragma unroll
            for (int mt = 0; mt < 4; mt++)
#pragma unroll
                for (int nt = 0; nt < 4; nt++)
                    mma_bf16(acc[mt][nt], af[mt], bf[nt]);
        }
    }

    // epilogue
    if (MODE == 0) {
#pragma unroll
        for (int mt = 0; mt < 4; mt++) {
            const int mA = m0 + wm * 64 + mt * 16 + g;
            float* oA = outf + ((size_t)b * O + mA) * NN + n0;
            float* oB = oA + (size_t)8 * NN;
#pragma unroll
            for (int nt = 0; nt < 4; nt++) {
                const int nc = wn * 32 + nt * 8 + tig * 2;
                *(float2*)&oA[nc] = make_float2(acc[mt][nt][0], acc[mt][nt][1]);
                *(float2*)&oB[nc] = make_float2(acc[mt][nt][2], acc[mt][nt][3]);
            }
        }
    } else {
        const int region = m0 >> 9;  // 0=q, 1=k, 2=v
        const float sc = (region == 0) ? 0.125f * LOG2E : 1.0f;
#pragma unroll
        for (int mt = 0; mt < 4; mt++) {
            const int mA = m0 + wm * 64 + mt * 16 + g;
#pragma unroll
            for (int nt = 0; nt < 4; nt++) {
                const int nc = n0 + wn * 32 + nt * 8 + tig * 2;
                float v0 = acc[mt][nt][0] * sc;
                float v1 = acc[mt][nt][1] * sc;
                float v2 = acc[mt][nt][2] * sc;
                float v3 = acc[mt][nt][3] * sc;
                if (region < 2) {
                    float p0 = __shfl_down_sync(0xffffffffu, v0, 4);
                    float p1 = __shfl_down_sync(0xffffffffu, v1, 4);
                    float p2 = __shfl_down_sync(0xffffffffu, v2, 4);
                    float p3 = __shfl_down_sync(0xffffffffu, v3, 4);
                    if (!(g & 1)) {
                        const int cw = mA >> 1;
                        size_t base0 = ((size_t)b * NN + nc) * (2 * CCW);
                        size_t base1 = base0 + 2 * CCW;
                        qkT[base0 + cw]     = packbf(v0, p0);
                        qkT[base0 + cw + 4] = packbf(v2, p2);
                        qkT[base1 + cw]     = packbf(v1, p1);
                        qkT[base1 + cw + 4] = packbf(v3, p3);
                    }
                } else {
                    const int ch = mA - 2 * CC;
                    vN[((size_t)b * CC + ch) * (NN / 2) + (nc >> 1)] =
                        packbf(v0, v1);
                    vN[((size_t)b * CC + ch + 8) * (NN / 2) + (nc >> 1)] =
                        packbf(v2, v3);
                }
            }
        }
    }
}

// ---------------------------------------------------------------------------
// Flash attention bf16 (proven config): ldmatrix Q/K/V, double-buffered
// cp.async K/V, log2-domain softmax (q pre-scaled by 1/8*log2e).
// SMEM: Qs [128][36], Ks[2][128][36], Vs[2][64][68] = 90112 B, 2 CTAs/SM.
// ---------------------------------------------------------------------------
#define AQ_OFF 0
#define AK_OFF 4608
#define AV_OFF 13824
#define ATTN_SMEM ((13824 + 2 * 4352) * 4)  // 90112 B

__global__ __launch_bounds__(256, 2) void attn_mma(
    const uint32_t* __restrict__ qkT, const uint32_t* __restrict__ vN,
    uint32_t* __restrict__ attT) {
    extern __shared__ uint32_t smw[];
    uint32_t* Qs = smw + AQ_OFF;

    const int qb = blockIdx.x, h = blockIdx.y, b = blockIdx.z;
    const int tid = threadIdx.x, lane = tid & 31;
    const int g = lane >> 2, tig = lane & 3;
    const int w16 = (tid >> 5) * 16;

    const int ri = lane & 7, mi = lane >> 3;
    const int arow = (mi & 1) * 8 + ri, aword = (mi >> 1) * 4;
    const int brow = (mi >> 1) * 8 + ri, bword = (mi & 1) * 4;

    auto issueKV = [&](int buf, int kb) {
        uint32_t* Ks = smw + AK_OFF + buf * 4608;
        uint32_t* Vs = smw + AV_OFF + buf * 4352;
        const uint32_t* kg = qkT + ((size_t)b * NN + kb * 128) * (2 * CCW) +
                             256 + h * 32;
#pragma unroll
        for (int p = 0; p < 4; p++) {
            int idx = p * 256 + tid;
            int n = idx >> 3, q4 = (idx & 7) * 4;
            cp16(&Ks[n * 36 + q4], &kg[(size_t)n * (2 * CCW) + q4]);
        }
        const uint32_t* vg = vN + ((size_t)b * CC + h * 64) * (NN / 2) + kb * 64;
#pragma unroll
        for (int p = 0; p < 4; p++) {
            int idx = p * 256 + tid;
            int dv = idx >> 4, j4 = (idx & 15) * 4;
            cp16(&Vs[dv * 68 + j4], &vg[(size_t)dv * (NN / 2) + j4]);
        }
    };

    // prologue: Q + KV(0) in group 0
    {
        const uint32_t* qg = qkT + ((size_t)b * NN + qb * 128) * (2 * CCW) + h * 32;
#pragma unroll
        for (int p = 0; p < 4; p++) {
            int idx = p * 256 + tid;
            int n = idx >> 3, q4 = (idx & 7) * 4;
            cp16(&Qs[n * 36 + q4], &qg[(size_t)n * (2 * CCW) + q4]);
        }
        issueKV(0, 0);
        CP_COMMIT();
    }

    float m0 = -1e30f, m1 = -1e30f, l0 = 0.f, l1 = 0.f;
    float o[8][4];
#pragma unroll
    for (int nt = 0; nt < 8; nt++)
#pragma unroll
        for (int e = 0; e < 4; e++) o[nt][e] = 0.f;

    for (int kb = 0; kb < 8; kb++) {
        __syncthreads();
        if (kb + 1 < 8) {
            issueKV((kb + 1) & 1, kb + 1);
            CP_COMMIT();
            CP_WAIT(1);
        } else {
            CP_WAIT(0);
        }
        __syncthreads();

        const uint32_t* Ks = smw + AK_OFF + (kb & 1) * 4608;
        const uint32_t* Vs = smw + AV_OFF + (kb & 1) * 4352;

        // S = Q K^T : 4 k16-steps over d=64 (log2-scaled logits)
        float s[16][4];
#pragma unroll
        for (int nt = 0; nt < 16; nt++)
#pragma unroll
            for (int e = 0; e < 4; e++) s[nt][e] = 0.f;
#pragma unroll
        for (int ks = 0; ks < 4; ks++) {
            uint32_t af[4];
            ldm_x4(af, &Qs[(w16 + arow) * 36 + ks * 8 + aword]);
#pragma unroll
            for (int np = 0; np < 8; np++) {
                uint32_t t[4];
                ldm_x4(t, &Ks[(np * 16 + brow) * 36 + ks * 8 + bword]);
                mma_bf16(s[2 * np], af, t);
                mma_bf16(s[2 * np + 1], af, t + 2);
            }
        }

        // online softmax in log2 domain (rows g / g+8, quad shfl)
        float rm0 = -1e30f, rm1 = -1e30f;
#pragma unroll
        for (int nt = 0; nt < 16; nt++) {
            rm0 = fmaxf(rm0, fmaxf(s[nt][0], s[nt][1]));
            rm1 = fmaxf(rm1, fmaxf(s[nt][2], s[nt][3]));
        }
        rm0 = fmaxf(rm0, __shfl_xor_sync(0xffffffffu, rm0, 1));
        rm0 = fmaxf(rm0, __shfl_xor_sync(0xffffffffu, rm0, 2));
        rm1 = fmaxf(rm1, __shfl_xor_sync(0xffffffffu, rm1, 1));
        rm1 = fmaxf(rm1, __shfl_xor_sync(0xffffffffu, rm1, 2));
        const float mn0 = fmaxf(m0, rm0), mn1 = fmaxf(m1, rm1);
        const float al0 = ex2f(m0 - mn0), al1 = ex2f(m1 - mn1);
        m0 = mn0; m1 = mn1;
        float sum0 = 0.f, sum1 = 0.f;
#pragma unroll
        for (int nt = 0; nt < 16; nt++) {
            s[nt][0] = ex2f(s[nt][0] - mn0);
            s[nt][1] = ex2f(s[nt][1] - mn0);
            s[nt][2] = ex2f(s[nt][2] - mn1);
            s[nt][3] = ex2f(s[nt][3] - mn1);
            sum0 += s[nt][0] + s[nt][1];
            sum1 += s[nt][2] + s[nt][3];
        }
        sum0 += __shfl_xor_sync(0xffffffffu, sum0, 1);
        sum0 += __shfl_xor_sync(0xffffffffu, sum0, 2);
        sum1 += __shfl_xor_sync(0xffffffffu, sum1, 1);
        sum1 += __shfl_xor_sync(0xffffffffu, sum1, 2);
        l0 = l0 * al0 + sum0;
        l1 = l1 * al1 + sum1;
#pragma unroll
        for (int nt = 0; nt < 8; nt++) {
            o[nt][0] *= al0; o[nt][1] *= al0;
            o[nt][2] *= al1; o[nt][3] *= al1;
        }

        // O += P V^T : P packs straight from C-frags
#pragma unroll
        for (int i = 0; i < 8; i++) {
            uint32_t af[4];
            af[0] = packbf(s[2 * i][0], s[2 * i][1]);
            af[1] = packbf(s[2 * i][2], s[2 * i][3]);
            af[2] = packbf(s[2 * i + 1][0], s[2 * i + 1][1]);
            af[3] = packbf(s[2 * i + 1][2], s[2 * i + 1][3]);
#pragma unroll
            for (int nvp = 0; nvp < 4; nvp++) {
                uint32_t t[4];
                ldm_x4(t, &Vs[(nvp * 16 + brow) * 68 + i * 8 + bword]);
                mma_bf16(o[2 * nvp], af, t);
                mma_bf16(o[2 * nvp + 1], af, t + 2);
            }
        }
    }

    // epilogue: attT[b][n][cword]
    const float inv0 = 1.f / l0, inv1 = 1.f / l1;
    uint32_t* og = attT + ((size_t)b * NN + qb * 128 + w16 + g) * CCW + h * 32;
    uint32_t* og8 = og + (size_t)8 * CCW;
#pragma unroll
    for (int nv = 0; nv < 8; nv++) {
        og[nv * 4 + tig]  = packbf(o[nv][0] * inv0, o[nv][1] * inv0);
        og8[nv * 4 + tig] = packbf(o[nv][2] * inv1, o[nv][3] * inv1);
    }
}

// ---------------------------------------------------------------------------
extern "C" void kernel_launch(void* const* d_in, const int* in_sizes, int n_in,
                              void* d_out, int out_size) {
    const float* x = (const float*)d_in[0];
    const float* gamma = (const float*)d_in[1];
    const float* beta = (const float*)d_in[2];
    const float* qkv_w = (const float*)d_in[3];
    const float* qkv_b = (const float*)d_in[4];
    const float* proj_w = (const float*)d_in[5];
    const float* proj_b = (const float*)d_in[6];
    float* out = (float*)d_out;

    uint32_t *xnT, *qkT, *vN, *attT, *wq, *wp;
    cudaGetSymbolAddress((void**)&xnT, g_xnT);
    cudaGetSymbolAddress((void**)&qkT, g_qkT);
    cudaGetSymbolAddress((void**)&vN, g_vN);
    cudaGetSymbolAddress((void**)&attT, g_attT);
    cudaGetSymbolAddress((void**)&wq, g_wq);
    cudaGetSymbolAddress((void**)&wp, g_wp);

    // 1. Fused GroupNorm + weight->bf16 conversion (one launch)
    cudaFuncSetAttribute(gn_w2_kernel,
                         cudaFuncAttributeMaxDynamicSharedMemorySize, GN_SMEM);
    gn_w2_kernel<<<GN_BLOCKS + W_BLOCKS, 256, GN_SMEM>>>(
        x, gamma, beta, xnT, (const float4*)qkv_w, (const float4*)proj_w,
        (uint2*)wq, (uint2*)wp);

    // 2. QKV GEMM (CTA 128x128) -> qkT + vN
    cudaFuncSetAttribute(gemm_mma<1>,
                         cudaFuncAttributeMaxDynamicSharedMemorySize, GEMM_SMEM);
    cudaFuncSetAttribute(gemm_mma<0>,
                         cudaFuncAttributeMaxDynamicSharedMemorySize, GEMM_SMEM);
    dim3 gq(NN / 128, (3 * CC) / 128, BQ);
    gemm_mma<1><<<gq, 256, GEMM_SMEM>>>(wq, qkv_b, xnT, nullptr, nullptr,
                                        qkT, vN, 3 * CC);

    // 3. Flash attention -> attT (packed bf16)
    cudaFuncSetAttribute(attn_mma,
                         cudaFuncAttributeMaxDynamicSharedMemorySize, ATTN_SMEM);
    attn_mma<<<dim3(NN / 128, NH, BQ), 256, ATTN_SMEM>>>(qkT, vN, attT);

    // 4. Proj GEMM + residual (folded into acc init) -> fp32 out
    dim3 gp(NN / 128, CC / 128, BQ);
    gemm_mma<0><<<gp, 256, GEMM_SMEM>>>(wp, proj_b, attT, x, out,
                                        nullptr, nullptr, CC);
}